// round 1
// baseline (speedup 1.0000x reference)
#include <cuda_runtime.h>
#include <cuda_bf16.h>

// RWKV WKV scan. B=8, S=2048, H=2048.
// Outputs (concatenated in d_out): output[B,S,H], m[B,H], num[B,H], den[B,H].
// One thread per (b,h) channel, sequential over t. All log-domain values
// pre-scaled by log2(e) so exponentials are bare EX2 MUFU ops.

#define WKV_B 8
#define WKV_S 2048
#define WKV_H 2048

__device__ __forceinline__ float ex2(float x) {
    float r;
    asm("ex2.approx.ftz.f32 %0, %1;" : "=f"(r) : "f"(x));
    return r;
}

__global__ void __launch_bounds__(64, 1) wkv_kernel(
    const float* __restrict__ time_decay,  // [H]
    const float* __restrict__ k,           // [B,S,H]
    const float* __restrict__ time_first,  // [H]
    const float* __restrict__ v,           // [B,S,H]
    const float* __restrict__ m0,          // [B,H]
    const float* __restrict__ n0,          // [B,H]
    const float* __restrict__ d0,          // [B,H]
    float* __restrict__ out)               // [B*S*H + 3*B*H]
{
    const int idx = blockIdx.x * blockDim.x + threadIdx.x;   // 0..B*H-1
    const int h = idx & (WKV_H - 1);
    const int b = idx >> 11;  // H = 2048 = 2^11

    const float L2E = 1.4426950408889634f;

    // td = -exp(time_decay), then scale to base-2 domain.
    const float td = -__expf(time_decay[h]) * L2E;
    const float tf = time_first[h] * L2E;

    float m   = m0[idx] * L2E;
    float num = n0[idx];
    float den = d0[idx];

    const int base = b * (WKV_S * WKV_H) + h;
    const float* __restrict__ kp = k + base;
    const float* __restrict__ vp = v + base;
    float* __restrict__ op = out + base;

#pragma unroll 4
    for (int t = 0; t < WKV_S; ++t) {
        const int off = t * WKV_H;
        const float kt = kp[off] * L2E;
        const float vt = vp[off];

        // ---- output branch (time_first bonus, pre-update state) ----
        const float btf = kt + tf;
        const float mo  = fmaxf(m, btf);
        const float e1o = ex2(m - mo);
        const float e2o = ex2(btf - mo);
        const float on  = fmaf(e1o, num, e2o * vt);
        const float od  = fmaf(e1o, den, e2o);
        op[off] = __fdividef(on, od);

        // ---- state branch (decay) ----
        const float a  = m + td;
        const float ms = fmaxf(a, kt);
        const float e1 = ex2(a - ms);
        const float e2 = ex2(kt - ms);
        num = fmaf(e1, num, e2 * vt);
        den = fmaf(e1, den, e2);
        m   = ms;
    }

    // Final states after the full output tensor.
    float* __restrict__ st = out + (size_t)WKV_B * WKV_S * WKV_H;
    const int BH = WKV_B * WKV_H;
    st[idx]          = m * (1.0f / L2E);
    st[BH + idx]     = num;
    st[2 * BH + idx] = den;
}

extern "C" void kernel_launch(void* const* d_in, const int* in_sizes, int n_in,
                              void* d_out, int out_size) {
    const float* time_decay = (const float*)d_in[0];
    const float* key        = (const float*)d_in[1];
    const float* time_first = (const float*)d_in[2];
    const float* value      = (const float*)d_in[3];
    const float* max_state  = (const float*)d_in[4];
    const float* num_state  = (const float*)d_in[5];
    const float* den_state  = (const float*)d_in[6];
    float* out = (float*)d_out;

    const int total = WKV_B * WKV_H;      // 16384 threads
    const int block = 64;
    const int grid = total / block;       // 256 blocks
    wkv_kernel<<<grid, block>>>(time_decay, key, time_first, value,
                                max_state, num_state, den_state, out);
}

// round 3
// speedup vs baseline: 2.4324x; 2.4324x over previous
#include <cuda_runtime.h>
#include <cuda_bf16.h>

// RWKV WKV scan. B=8, S=2048, H=2048.
// Outputs (concatenated in d_out): output[B,S,H], m[B,H], num[B,H], den[B,H].
// One thread per (b,h) channel, sequential over t.
// R2: G=16 double-buffered register prefetch, 2-EX2 formulation (one exp is
// always 1 since the max subtracts it out), 128x128 launch for SMSP balance.

#define WKV_B 8
#define WKV_S 2048
#define WKV_H 2048
#define G 16

__device__ __forceinline__ float ex2(float x) {
    float r;
    asm("ex2.approx.ftz.f32 %0, %1;" : "=f"(r) : "f"(x));
    return r;
}

__global__ void __launch_bounds__(128, 1) wkv_kernel(
    const float* __restrict__ time_decay,  // [H]
    const float* __restrict__ k,           // [B,S,H]
    const float* __restrict__ time_first,  // [H]
    const float* __restrict__ v,           // [B,S,H]
    const float* __restrict__ m0,          // [B,H]
    const float* __restrict__ n0,          // [B,H]
    const float* __restrict__ d0,          // [B,H]
    float* __restrict__ out)               // [B*S*H + 3*B*H]
{
    const int idx = blockIdx.x * blockDim.x + threadIdx.x;   // 0..B*H-1
    const int h = idx & (WKV_H - 1);
    const int b = idx >> 11;  // H = 2048 = 2^11

    const float L2E = 1.4426950408889634f;

    const float td = -__expf(time_decay[h]) * L2E;   // base-2 log domain
    const float tf = time_first[h] * L2E;

    float m   = m0[idx] * L2E;
    float num = n0[idx];
    float den = d0[idx];

    const int base = b * (WKV_S * WKV_H) + h;
    const float* __restrict__ kp = k + base;
    const float* __restrict__ vp = v + base;
    float* __restrict__ op = out + base;

    float kb[G], vb[G];
#pragma unroll
    for (int g = 0; g < G; ++g) {
        kb[g] = kp[g * WKV_H] * L2E;
        vb[g] = vp[g * WKV_H];
    }

    for (int t0 = 0; t0 < WKV_S; t0 += G) {
        // Prefetch next group while computing this one.
        float kn[G], vn[G];
        const bool more = (t0 + G) < WKV_S;
        if (more) {
#pragma unroll
            for (int g = 0; g < G; ++g) {
                kn[g] = kp[(t0 + G + g) * WKV_H] * L2E;
                vn[g] = vp[(t0 + G + g) * WKV_H];
            }
        }

#pragma unroll
        for (int g = 0; g < G; ++g) {
            const float kt = kb[g];
            const float vt = vb[g];

            // ---- output branch: mo = max(m, kt+tf); one exp is exp(0)=1 ----
            const float btf = kt + tf;
            const float d1  = m - btf;
            const float eo  = ex2(-fabsf(d1));
            const float e1o = (d1 >= 0.0f) ? 1.0f : eo;
            const float e2o = (d1 >= 0.0f) ? eo : 1.0f;
            const float on  = fmaf(e1o, num, e2o * vt);
            const float od  = fmaf(e1o, den, e2o);
            op[(t0 + g) * WKV_H] = __fdividef(on, od);

            // ---- state branch: ms = max(m+td, kt); same trick ----
            const float a  = m + td;
            const float d2 = a - kt;
            const float es = ex2(-fabsf(d2));
            const float e1 = (d2 >= 0.0f) ? 1.0f : es;
            const float e2 = (d2 >= 0.0f) ? es : 1.0f;
            m   = fmaxf(a, kt);
            num = fmaf(e1, num, e2 * vt);
            den = fmaf(e1, den, e2);
        }

        if (more) {
#pragma unroll
            for (int g = 0; g < G; ++g) { kb[g] = kn[g]; vb[g] = vn[g]; }
        }
    }

    // Final states after the full output tensor.
    float* __restrict__ st = out + (size_t)WKV_B * WKV_S * WKV_H;
    const int BH = WKV_B * WKV_H;
    st[idx]          = m * (1.0f / L2E);
    st[BH + idx]     = num;
    st[2 * BH + idx] = den;
}

extern "C" void kernel_launch(void* const* d_in, const int* in_sizes, int n_in,
                              void* d_out, int out_size) {
    const float* time_decay = (const float*)d_in[0];
    const float* key        = (const float*)d_in[1];
    const float* time_first = (const float*)d_in[2];
    const float* value      = (const float*)d_in[3];
    const float* max_state  = (const float*)d_in[4];
    const float* num_state  = (const float*)d_in[5];
    const float* den_state  = (const float*)d_in[6];
    float* out = (float*)d_out;

    const int total = WKV_B * WKV_H;      // 16384 threads
    const int block = 128;                // 4 warps -> one per SMSP
    const int grid  = total / block;      // 128 blocks, 1 per SM
    wkv_kernel<<<grid, block>>>(time_decay, key, time_first, value,
                                max_state, num_state, den_state, out);
}

// round 4
// speedup vs baseline: 2.8065x; 1.1538x over previous
#include <cuda_runtime.h>
#include <cuda_bf16.h>
#include <math_constants.h>

// RWKV WKV scan. B=8, S=2048, H=2048.
// R3: chunked associative scan over the sequence.
//   K1: per-chunk summaries from identity state (C*B*H threads).
//   K2: per-channel prefix combine over C summaries.
//   K3: per-chunk output pass from exact entry state (re-reads k,v).
// All log-domain values scaled by log2(e) so exps are bare EX2.

#define WKV_B 8
#define WKV_S 2048
#define WKV_H 2048
#define BH (WKV_B * WKV_H)          // 16384
#define CHUNKS 8
#define CLEN (WKV_S / CHUNKS)       // 256
#define G4 4

__device__ float g_sum_m[CHUNKS * BH];
__device__ float g_sum_n[CHUNKS * BH];
__device__ float g_sum_d[CHUNKS * BH];
__device__ float g_pre_m[CHUNKS * BH];
__device__ float g_pre_n[CHUNKS * BH];
__device__ float g_pre_d[CHUNKS * BH];

__device__ __forceinline__ float ex2(float x) {
    float r;
    asm("ex2.approx.ftz.f32 %0, %1;" : "=f"(r) : "f"(x));
    return r;
}

// ---------------- Kernel 1: chunk summaries (state-only scan) ----------------
__global__ void __launch_bounds__(128, 7) wkv_sum_kernel(
    const float* __restrict__ time_decay,
    const float* __restrict__ k,
    const float* __restrict__ v)
{
    const int tid = blockIdx.x * blockDim.x + threadIdx.x;  // 0..C*BH-1
    const int ch  = tid & (BH - 1);
    const int c   = tid >> 14;            // BH = 2^14
    const int h   = ch & (WKV_H - 1);
    const int b   = ch >> 11;

    const float L2E = 1.4426950408889634f;
    const float td  = -__expf(time_decay[h]) * L2E;

    float m   = -CUDART_INF_F;
    float num = 0.0f;
    float den = 0.0f;

    const int base = b * (WKV_S * WKV_H) + (c * CLEN) * WKV_H + h;
    const float* __restrict__ kp = k + base;
    const float* __restrict__ vp = v + base;

    float kb[G4], vb[G4];
#pragma unroll
    for (int g = 0; g < G4; ++g) {
        kb[g] = kp[g * WKV_H] * L2E;
        vb[g] = vp[g * WKV_H];
    }

    for (int t0 = 0; t0 < CLEN; t0 += G4) {
        float kn[G4], vn[G4];
        const bool more = (t0 + G4) < CLEN;
        if (more) {
#pragma unroll
            for (int g = 0; g < G4; ++g) {
                kn[g] = kp[(t0 + G4 + g) * WKV_H] * L2E;
                vn[g] = vp[(t0 + G4 + g) * WKV_H];
            }
        }
#pragma unroll
        for (int g = 0; g < G4; ++g) {
            const float kt = kb[g];
            const float vt = vb[g];
            const float a  = m + td;
            const float d2 = a - kt;
            const float es = ex2(-fabsf(d2));
            const float e1 = (d2 >= 0.0f) ? 1.0f : es;
            const float e2 = (d2 >= 0.0f) ? es : 1.0f;
            m   = fmaxf(a, kt);
            num = fmaf(e1, num, e2 * vt);
            den = fmaf(e1, den, e2);
        }
        if (more) {
#pragma unroll
            for (int g = 0; g < G4; ++g) { kb[g] = kn[g]; vb[g] = vn[g]; }
        }
    }

    g_sum_m[tid] = m;
    g_sum_n[tid] = num;
    g_sum_d[tid] = den;
}

// ---------------- Kernel 2: per-channel prefix over chunk summaries ----------
__global__ void __launch_bounds__(256) wkv_prefix_kernel(
    const float* __restrict__ time_decay,
    const float* __restrict__ m0,
    const float* __restrict__ n0,
    const float* __restrict__ d0)
{
    const int ch = blockIdx.x * blockDim.x + threadIdx.x;   // 0..BH-1
    const int h  = ch & (WKV_H - 1);

    const float L2E = 1.4426950408889634f;
    const float td  = -__expf(time_decay[h]) * L2E;
    const float Ltd = (float)CLEN * td;

    float pm = m0[ch] * L2E;
    float pn = n0[ch];
    float pd = d0[ch];

#pragma unroll
    for (int c = 0; c < CHUNKS; ++c) {
        const int idx = c * BH + ch;
        g_pre_m[idx] = pm;
        g_pre_n[idx] = pn;
        g_pre_d[idx] = pd;
        if (c < CHUNKS - 1) {
            const float sm = g_sum_m[idx];
            const float sn = g_sum_n[idx];
            const float sd = g_sum_d[idx];
            const float a  = pm + Ltd;          // prefix decayed through L steps
            const float mo = fmaxf(a, sm);
            const float e1 = ex2(a - mo);
            const float e2 = ex2(sm - mo);
            pn = fmaf(e1, pn, e2 * sn);
            pd = fmaf(e1, pd, e2 * sd);
            pm = mo;
        }
    }
}

// ---------------- Kernel 3: outputs from exact chunk-entry state -------------
__global__ void __launch_bounds__(128, 7) wkv_out_kernel(
    const float* __restrict__ time_decay,
    const float* __restrict__ k,
    const float* __restrict__ time_first,
    const float* __restrict__ v,
    float* __restrict__ out)
{
    const int tid = blockIdx.x * blockDim.x + threadIdx.x;  // 0..C*BH-1
    const int ch  = tid & (BH - 1);
    const int c   = tid >> 14;
    const int h   = ch & (WKV_H - 1);
    const int b   = ch >> 11;

    const float L2E = 1.4426950408889634f;
    const float td  = -__expf(time_decay[h]) * L2E;
    const float tf  = time_first[h] * L2E;

    float m   = g_pre_m[tid];
    float num = g_pre_n[tid];
    float den = g_pre_d[tid];

    const int base = b * (WKV_S * WKV_H) + (c * CLEN) * WKV_H + h;
    const float* __restrict__ kp = k + base;
    const float* __restrict__ vp = v + base;
    float* __restrict__ op = out + base;

    float kb[G4], vb[G4];
#pragma unroll
    for (int g = 0; g < G4; ++g) {
        kb[g] = kp[g * WKV_H] * L2E;
        vb[g] = vp[g * WKV_H];
    }

    for (int t0 = 0; t0 < CLEN; t0 += G4) {
        float kn[G4], vn[G4];
        const bool more = (t0 + G4) < CLEN;
        if (more) {
#pragma unroll
            for (int g = 0; g < G4; ++g) {
                kn[g] = kp[(t0 + G4 + g) * WKV_H] * L2E;
                vn[g] = vp[(t0 + G4 + g) * WKV_H];
            }
        }
#pragma unroll
        for (int g = 0; g < G4; ++g) {
            const float kt = kb[g];
            const float vt = vb[g];

            // output branch
            const float btf = kt + tf;
            const float d1  = m - btf;
            const float eo  = ex2(-fabsf(d1));
            const float e1o = (d1 >= 0.0f) ? 1.0f : eo;
            const float e2o = (d1 >= 0.0f) ? eo : 1.0f;
            const float on  = fmaf(e1o, num, e2o * vt);
            const float od  = fmaf(e1o, den, e2o);
            op[(t0 + g) * WKV_H] = __fdividef(on, od);

            // state branch
            const float a  = m + td;
            const float d2 = a - kt;
            const float es = ex2(-fabsf(d2));
            const float e1 = (d2 >= 0.0f) ? 1.0f : es;
            const float e2 = (d2 >= 0.0f) ? es : 1.0f;
            m   = fmaxf(a, kt);
            num = fmaf(e1, num, e2 * vt);
            den = fmaf(e1, den, e2);
        }
        if (more) {
#pragma unroll
            for (int g = 0; g < G4; ++g) { kb[g] = kn[g]; vb[g] = vn[g]; }
        }
    }

    if (c == CHUNKS - 1) {
        float* __restrict__ st = out + (size_t)WKV_B * WKV_S * WKV_H;
        st[ch]          = m * (1.0f / L2E);
        st[BH + ch]     = num;
        st[2 * BH + ch] = den;
    }
}

extern "C" void kernel_launch(void* const* d_in, const int* in_sizes, int n_in,
                              void* d_out, int out_size) {
    const float* time_decay = (const float*)d_in[0];
    const float* key        = (const float*)d_in[1];
    const float* time_first = (const float*)d_in[2];
    const float* value      = (const float*)d_in[3];
    const float* max_state  = (const float*)d_in[4];
    const float* num_state  = (const float*)d_in[5];
    const float* den_state  = (const float*)d_in[6];
    float* out = (float*)d_out;

    const int total = CHUNKS * BH;        // 131072
    wkv_sum_kernel<<<total / 128, 128>>>(time_decay, key, value);
    wkv_prefix_kernel<<<BH / 256, 256>>>(time_decay, max_state, num_state, den_state);
    wkv_out_kernel<<<total / 128, 128>>>(time_decay, key, time_first, value, out);
}